// round 15
// baseline (speedup 1.0000x reference)
#include <cuda_runtime.h>
#include <cuda_bf16.h>
#include <cuda_fp16.h>
#include <cstdint>

#define N_NODES 100000
#define F_IN    512
#define HID     256
#define N_CLS   32
#define N_EDGES 3200000
#define KSTEPS  10
#define NBLK    ((N_NODES + 255) / 256)   // 391
#define SPMV_BLOCKS 3125                  // 4 nodes per warp

// ---------------- device scratch ----------------
__device__ __align__(128) float   g_h0[(size_t)N_NODES * N_CLS];          // fp32 h0 from MLP
__device__ __align__(128) __half2 g_ps[KSTEPS + 1][(size_t)N_NODES * 16]; // p_k history (fp16)
__device__ __align__(128) int     g_deg[N_NODES];
__device__ __align__(128) int     g_rowptr[N_NODES + 1];
__device__ __align__(128) int     g_pos[N_NODES];
__device__ __align__(128) int     g_csr_idx[N_EDGES];
__device__ __align__(128) int     g_bsum[512];
__device__ __align__(128) int     g_boff[512];
__device__ __align__(128) __nv_bfloat16 g_w1t_hi[(size_t)HID * F_IN];
__device__ __align__(128) __nv_bfloat16 g_w1t_lo[(size_t)HID * F_IN];
__device__ __align__(128) __nv_bfloat16 g_w2t_hi[(size_t)N_CLS * HID];
__device__ __align__(128) __nv_bfloat16 g_w2t_lo[(size_t)N_CLS * HID];
__device__ int g_is64;

// ---------------- edge index dtype sniff ----------------
__global__ void k_sniff(const unsigned* __restrict__ raw) {
    unsigned orv = 0;
#pragma unroll
    for (int i = 0; i < 16; i++) orv |= raw[2 * i + 1];
    g_is64 = (orv == 0u) ? 1 : 0;
}

__device__ __forceinline__ int edge_at(const void* raw, size_t idx) {
    return g_is64 ? (int)((const long long*)raw)[idx] : ((const int*)raw)[idx];
}

__global__ void k_degcnt(const void* __restrict__ raw) {
    int e = blockIdx.x * blockDim.x + threadIdx.x;
    if (e < N_EDGES) atomicAdd(&g_deg[edge_at(raw, (size_t)N_EDGES + e)], 1);
}

__global__ void k_deg_zero() {
    int i = blockIdx.x * blockDim.x + threadIdx.x;
    if (i < N_NODES) g_deg[i] = 0;
}

// ---------------- parallel exclusive scan of g_deg -> g_rowptr/g_pos ----------------
__global__ __launch_bounds__(256) void k_scan1() {
    __shared__ int wsum[8];
    int tid = threadIdx.x;
    int i = blockIdx.x * 256 + tid;
    int v = (i < N_NODES) ? g_deg[i] : 0;
    int x = v;
#pragma unroll
    for (int o = 16; o; o >>= 1) x += __shfl_down_sync(0xffffffffu, x, o);
    if ((tid & 31) == 0) wsum[tid >> 5] = x;
    __syncthreads();
    if (tid < 8) {
        int y = wsum[tid];
#pragma unroll
        for (int o = 4; o; o >>= 1) y += __shfl_down_sync(0xffu, y, o);
        if (tid == 0) g_bsum[blockIdx.x] = y;
    }
}

__global__ __launch_bounds__(512) void k_scan2() {
    __shared__ int wsum[16];
    int tid = threadIdx.x;
    int lane = tid & 31, w = tid >> 5;
    int v = (tid < NBLK) ? g_bsum[tid] : 0;
    int x = v;
#pragma unroll
    for (int o = 1; o < 32; o <<= 1) {
        int t = __shfl_up_sync(0xffffffffu, x, o);
        if (lane >= o) x += t;
    }
    if (lane == 31) wsum[w] = x;
    __syncthreads();
    if (tid < 16) {
        int y = wsum[tid];
#pragma unroll
        for (int o = 1; o < 16; o <<= 1) {
            int t = __shfl_up_sync(0xffffu, y, o);
            if (tid >= o) y += t;
        }
        wsum[tid] = y;
    }
    __syncthreads();
    int pre = (w > 0) ? wsum[w - 1] : 0;
    int excl = pre + x - v;
    g_boff[tid] = excl;
    if (tid == NBLK) g_rowptr[N_NODES] = excl;
}

__global__ __launch_bounds__(256) void k_scan3() {
    __shared__ int wsum[8];
    int tid = threadIdx.x;
    int i = blockIdx.x * 256 + tid;
    int lane = tid & 31, w = tid >> 5;
    int v = (i < N_NODES) ? g_deg[i] : 0;
    int x = v;
#pragma unroll
    for (int o = 1; o < 32; o <<= 1) {
        int t = __shfl_up_sync(0xffffffffu, x, o);
        if (lane >= o) x += t;
    }
    if (lane == 31) wsum[w] = x;
    __syncthreads();
    if (tid < 8) {
        int y = wsum[tid];
#pragma unroll
        for (int o = 1; o < 8; o <<= 1) {
            int t = __shfl_up_sync(0xffu, y, o);
            if (tid >= o) y += t;
        }
        wsum[tid] = y;
    }
    __syncthreads();
    int pre = (w > 0) ? wsum[w - 1] : 0;
    int excl = g_boff[blockIdx.x] + pre + x - v;
    if (i < N_NODES) { g_rowptr[i] = excl; g_pos[i] = excl; }
}

__global__ void k_fill(const void* __restrict__ raw) {
    int e = blockIdx.x * blockDim.x + threadIdx.x;
    if (e >= N_EDGES) return;
    int s = edge_at(raw, e);
    int d = edge_at(raw, (size_t)N_EDGES + e);
    int p = atomicAdd(&g_pos[d], 1);
    g_csr_idx[p] = s;
}

// ---------------- weight conversions ----------------
__global__ void k_w1cvt(const float* __restrict__ W1) {
    int i = blockIdx.x * blockDim.x + threadIdx.x;
    if (i >= F_IN * HID) return;
    int k = i / HID, n = i % HID;
    float v = W1[i];
    __nv_bfloat16 h = __float2bfloat16(v);
    g_w1t_hi[(size_t)n * F_IN + k] = h;
    g_w1t_lo[(size_t)n * F_IN + k] = __float2bfloat16(v - __bfloat162float(h));
}

__global__ void k_w2cvt(const float* __restrict__ W2) {
    int i = blockIdx.x * blockDim.x + threadIdx.x;
    if (i >= HID * N_CLS) return;
    int k = i / N_CLS, n = i % N_CLS;
    float v = W2[i];
    __nv_bfloat16 h = __float2bfloat16(v);
    g_w2t_hi[(size_t)n * HID + k] = h;
    g_w2t_lo[(size_t)n * HID + k] = __float2bfloat16(v - __bfloat162float(h));
}

// ---------------- fused MLP: h0 = relu(x@W1+b1)@W2 + b2 ----------------
#define ST1  72
#define ST2  264

#define ASH_O   0u
#define ASL_O   18432u
#define BSH_O   36864u
#define BSL_O   73728u
#define ZHI_O   0u
#define ZLO_O   67584u
#define W2HI_O  135168u
#define W2LO_O  152064u
#define B2_O    168960u
#define BIAS_O  169088u
#define SMEM_T  170112u

#define MMA16816(c, a, b) \
    asm volatile("mma.sync.aligned.m16n8k16.row.col.f32.bf16.bf16.f32 " \
                 "{%0,%1,%2,%3},{%4,%5,%6,%7},{%8,%9},{%0,%1,%2,%3};" \
                 : "+f"((c)[0]), "+f"((c)[1]), "+f"((c)[2]), "+f"((c)[3]) \
                 : "r"((a)[0]), "r"((a)[1]), "r"((a)[2]), "r"((a)[3]), \
                   "r"((b)[0]), "r"((b)[1]))

__device__ __forceinline__ uint32_t pack_hi(float a, float b) {
    __nv_bfloat16 h0 = __float2bfloat16(a), h1 = __float2bfloat16(b);
    return (uint32_t)__bfloat16_as_ushort(h0) | ((uint32_t)__bfloat16_as_ushort(h1) << 16);
}
__device__ __forceinline__ uint32_t pack_lo(float a, float b) {
    __nv_bfloat16 h0 = __float2bfloat16(a), h1 = __float2bfloat16(b);
    float r0 = a - __bfloat162float(h0), r1 = b - __bfloat162float(h1);
    __nv_bfloat16 l0 = __float2bfloat16(r0), l1 = __float2bfloat16(r1);
    return (uint32_t)__bfloat16_as_ushort(l0) | ((uint32_t)__bfloat16_as_ushort(l1) << 16);
}

__global__ __launch_bounds__(256, 1) void k_mlp(const float* __restrict__ x,
                                                const float* __restrict__ b1,
                                                const float* __restrict__ b2) {
    extern __shared__ __align__(16) char sm[];
    __nv_bfloat16* as_hi = (__nv_bfloat16*)(sm + ASH_O);
    __nv_bfloat16* as_lo = (__nv_bfloat16*)(sm + ASL_O);
    __nv_bfloat16* bs_hi = (__nv_bfloat16*)(sm + BSH_O);
    __nv_bfloat16* bs_lo = (__nv_bfloat16*)(sm + BSL_O);
    uint32_t* zhi = (uint32_t*)(sm + ZHI_O);
    uint32_t* zlo = (uint32_t*)(sm + ZLO_O);
    __nv_bfloat16* w2hi = (__nv_bfloat16*)(sm + W2HI_O);
    __nv_bfloat16* w2lo = (__nv_bfloat16*)(sm + W2LO_O);
    float* b2s = (float*)(sm + B2_O);
    float* bias_s = (float*)(sm + BIAS_O);

    const int tid = threadIdx.x;
    const int wid = tid >> 5, lane = tid & 31;
    const int gq = lane >> 2, tg = lane & 3;
    const int rowBase = blockIdx.x * 128;
    const int wr = (wid >> 2) * 64, wc = (wid & 3) * 64;

    bias_s[tid] = b1[tid];
    if (tid < N_CLS) b2s[tid] = b2[tid];
    for (int i = tid; i < 1024; i += 256) {
        int n = i >> 5, k8 = (i & 31) * 8;
        *(uint4*)(w2hi + n * ST2 + k8) = *(const uint4*)(g_w2t_hi + n * HID + k8);
        *(uint4*)(w2lo + n * ST2 + k8) = *(const uint4*)(g_w2t_lo + n * HID + k8);
    }

    float acc[4][8][4];
#pragma unroll
    for (int a = 0; a < 4; a++)
#pragma unroll
        for (int b = 0; b < 8; b++)
#pragma unroll
            for (int c = 0; c < 4; c++) acc[a][b][c] = 0.f;

    float4 aPre[8];
    {
#pragma unroll
        for (int j = 0; j < 8; j++) {
            int i = tid + 256 * j;
            int r = i >> 4, cc = (i & 15) * 4;
            int grow = rowBase + r;
            aPre[j] = make_float4(0.f, 0.f, 0.f, 0.f);
            if (grow < N_NODES)
                aPre[j] = *(const float4*)(x + (size_t)grow * F_IN + cc);
        }
    }

    for (int ch = 0; ch < 8; ch++) {
        const int k0 = ch * 64;
        __syncthreads();
#pragma unroll
        for (int j = 0; j < 8; j++) {
            int i = tid + 256 * j;
            int r = i >> 4, cc = (i & 15) * 4;
            float4 v = aPre[j];
            uint2 ph = make_uint2(pack_hi(v.x, v.y), pack_hi(v.z, v.w));
            uint2 pl = make_uint2(pack_lo(v.x, v.y), pack_lo(v.z, v.w));
            *(uint2*)(as_hi + r * ST1 + cc) = ph;
            *(uint2*)(as_lo + r * ST1 + cc) = pl;
        }
        for (int i = tid; i < 2048; i += 256) {
            int n = i >> 3, k8 = (i & 7) * 8;
            size_t gi = (size_t)n * F_IN + k0 + k8;
            *(uint4*)(bs_hi + n * ST1 + k8) = *(const uint4*)(g_w1t_hi + gi);
            *(uint4*)(bs_lo + n * ST1 + k8) = *(const uint4*)(g_w1t_lo + gi);
        }
        __syncthreads();

        if (ch < 7) {
            const int k1 = (ch + 1) * 64;
#pragma unroll
            for (int j = 0; j < 8; j++) {
                int i = tid + 256 * j;
                int r = i >> 4, cc = (i & 15) * 4;
                int grow = rowBase + r;
                aPre[j] = make_float4(0.f, 0.f, 0.f, 0.f);
                if (grow < N_NODES)
                    aPre[j] = *(const float4*)(x + (size_t)grow * F_IN + k1 + cc);
            }
        }

#pragma unroll
        for (int ks = 0; ks < 4; ks++) {
            const int ko = ks * 16;
            uint32_t ah[4][4], al[4][4];
#pragma unroll
            for (int mt = 0; mt < 4; mt++) {
                int r0 = wr + mt * 16 + gq;
                ah[mt][0] = *(const uint32_t*)(as_hi + r0 * ST1 + ko + 2 * tg);
                ah[mt][1] = *(const uint32_t*)(as_hi + (r0 + 8) * ST1 + ko + 2 * tg);
                ah[mt][2] = *(const uint32_t*)(as_hi + r0 * ST1 + ko + 8 + 2 * tg);
                ah[mt][3] = *(const uint32_t*)(as_hi + (r0 + 8) * ST1 + ko + 8 + 2 * tg);
                al[mt][0] = *(const uint32_t*)(as_lo + r0 * ST1 + ko + 2 * tg);
                al[mt][1] = *(const uint32_t*)(as_lo + (r0 + 8) * ST1 + ko + 2 * tg);
                al[mt][2] = *(const uint32_t*)(as_lo + r0 * ST1 + ko + 8 + 2 * tg);
                al[mt][3] = *(const uint32_t*)(as_lo + (r0 + 8) * ST1 + ko + 8 + 2 * tg);
            }
#pragma unroll
            for (int nt = 0; nt < 8; nt++) {
                int n0 = wc + nt * 8 + gq;
                uint32_t bh[2], bl[2];
                bh[0] = *(const uint32_t*)(bs_hi + n0 * ST1 + ko + 2 * tg);
                bh[1] = *(const uint32_t*)(bs_hi + n0 * ST1 + ko + 8 + 2 * tg);
                bl[0] = *(const uint32_t*)(bs_lo + n0 * ST1 + ko + 2 * tg);
                bl[1] = *(const uint32_t*)(bs_lo + n0 * ST1 + ko + 8 + 2 * tg);
#pragma unroll
                for (int mt = 0; mt < 4; mt++) {
                    MMA16816(acc[mt][nt], ah[mt], bh);
                    MMA16816(acc[mt][nt], ah[mt], bl);
                    MMA16816(acc[mt][nt], al[mt], bh);
                }
            }
        }
    }

    __syncthreads();

#pragma unroll
    for (int mt = 0; mt < 4; mt++) {
        int r0 = wr + mt * 16 + gq;
        int r1 = r0 + 8;
#pragma unroll
        for (int nt = 0; nt < 8; nt++) {
            int cl = wc + nt * 8 + 2 * tg;
            float bx = bias_s[cl], by = bias_s[cl + 1];
            float o0 = fmaxf(acc[mt][nt][0] + bx, 0.f);
            float o1 = fmaxf(acc[mt][nt][1] + by, 0.f);
            float o2 = fmaxf(acc[mt][nt][2] + bx, 0.f);
            float o3 = fmaxf(acc[mt][nt][3] + by, 0.f);
            int w0 = r0 * 132 + (cl >> 1);
            int w1 = r1 * 132 + (cl >> 1);
            zhi[w0] = pack_hi(o0, o1); zlo[w0] = pack_lo(o0, o1);
            zhi[w1] = pack_hi(o2, o3); zlo[w1] = pack_lo(o2, o3);
        }
    }
    __syncthreads();

    float acc2[4][4];
#pragma unroll
    for (int a = 0; a < 4; a++)
#pragma unroll
        for (int c = 0; c < 4; c++) acc2[a][c] = 0.f;

    const int rl0 = wid * 16 + gq;
#pragma unroll
    for (int ks = 0; ks < 16; ks++) {
        const int kw = ks * 8 + tg;
        uint32_t ah[4], al[4];
        ah[0] = zhi[rl0 * 132 + kw];
        ah[1] = zhi[(rl0 + 8) * 132 + kw];
        ah[2] = zhi[rl0 * 132 + kw + 4];
        ah[3] = zhi[(rl0 + 8) * 132 + kw + 4];
        al[0] = zlo[rl0 * 132 + kw];
        al[1] = zlo[(rl0 + 8) * 132 + kw];
        al[2] = zlo[rl0 * 132 + kw + 4];
        al[3] = zlo[(rl0 + 8) * 132 + kw + 4];
#pragma unroll
        for (int nt = 0; nt < 4; nt++) {
            int n0 = nt * 8 + gq;
            uint32_t bh[2], bl[2];
            bh[0] = *(const uint32_t*)(w2hi + n0 * ST2 + ks * 16 + 2 * tg);
            bh[1] = *(const uint32_t*)(w2hi + n0 * ST2 + ks * 16 + 8 + 2 * tg);
            bl[0] = *(const uint32_t*)(w2lo + n0 * ST2 + ks * 16 + 2 * tg);
            bl[1] = *(const uint32_t*)(w2lo + n0 * ST2 + ks * 16 + 8 + 2 * tg);
            MMA16816(acc2[nt], ah, bh);
            MMA16816(acc2[nt], ah, bl);
            MMA16816(acc2[nt], al, bh);
        }
    }

    int row0 = rowBase + rl0, row1 = row0 + 8;
#pragma unroll
    for (int nt = 0; nt < 4; nt++) {
        int cl = nt * 8 + 2 * tg;
        float bx = b2s[cl], by = b2s[cl + 1];
        if (row0 < N_NODES)
            *(float2*)(g_h0 + (size_t)row0 * N_CLS + cl) =
                make_float2(acc2[nt][0] + bx, acc2[nt][1] + by);
        if (row1 < N_NODES)
            *(float2*)(g_h0 + (size_t)row1 * N_CLS + cl) =
                make_float2(acc2[nt][2] + bx, acc2[nt][3] + by);
    }
}

// ---------------- scale: p_0 = fp16(dinv * h0) ----------------
__global__ void k_scale() {
    int i = blockIdx.x * blockDim.x + threadIdx.x;   // one half2 (2 classes)
    if (i >= N_NODES * 16) return;
    int n = i >> 4;
    float di = rsqrtf(1.0f + (float)g_deg[n]);
    float2 v = *(float2*)(g_h0 + (size_t)i * 2);
    g_ps[0][i] = __floats2half2_rn(v.x * di, v.y * di);
}

// ---------------- SpMV step: p_k = A_norm * p_{k-1} (4 nodes per warp) ----------------
// 4 lanes per edge; lane q = lane&3 owns classes [8q, 8q+8); gslot = lane>>2
__global__ __launch_bounds__(256) void k_spmv(int kidx) {
    const __half2* __restrict__ pc = g_ps[kidx - 1];
    __half2* __restrict__ pn = g_ps[kidx];

    const int NW = SPMV_BLOCKS * 8;   // total warps = 25000
    const int gw = blockIdx.x * 8 + (threadIdx.x >> 5);
    const int lane = threadIdx.x & 31;
    const int q = lane & 3;
    const int gslot = lane >> 2;

    for (int n = gw; n < N_NODES; n += NW) {
        int beg = g_rowptr[n], end = g_rowptr[n + 1];

        float acc[8];
#pragma unroll
        for (int j = 0; j < 8; j++) acc[j] = 0.f;

        int e = beg;
        for (; e + 16 <= end; e += 16) {
            int s0 = g_csr_idx[e + gslot];
            int s1 = g_csr_idx[e + 8 + gslot];
            uint4 r0 = *(const uint4*)(pc + (size_t)s0 * 16 + q * 4);
            uint4 r1 = *(const uint4*)(pc + (size_t)s1 * 16 + q * 4);
            float2 f;
            f = __half22float2(*(__half2*)&r0.x); acc[0] += f.x; acc[1] += f.y;
            f = __half22float2(*(__half2*)&r0.y); acc[2] += f.x; acc[3] += f.y;
            f = __half22float2(*(__half2*)&r0.z); acc[4] += f.x; acc[5] += f.y;
            f = __half22float2(*(__half2*)&r0.w); acc[6] += f.x; acc[7] += f.y;
            f = __half22float2(*(__half2*)&r1.x); acc[0] += f.x; acc[1] += f.y;
            f = __half22float2(*(__half2*)&r1.y); acc[2] += f.x; acc[3] += f.y;
            f = __half22float2(*(__half2*)&r1.z); acc[4] += f.x; acc[5] += f.y;
            f = __half22float2(*(__half2*)&r1.w); acc[6] += f.x; acc[7] += f.y;
        }
        for (; e < end; e += 8) {
            int ee = e + gslot;
            if (ee < end) {
                int s = g_csr_idx[ee];
                uint4 r0 = *(const uint4*)(pc + (size_t)s * 16 + q * 4);
                float2 f;
                f = __half22float2(*(__half2*)&r0.x); acc[0] += f.x; acc[1] += f.y;
                f = __half22float2(*(__half2*)&r0.y); acc[2] += f.x; acc[3] += f.y;
                f = __half22float2(*(__half2*)&r0.z); acc[4] += f.x; acc[5] += f.y;
                f = __half22float2(*(__half2*)&r0.w); acc[6] += f.x; acc[7] += f.y;
            }
        }

#pragma unroll
        for (int off = 4; off <= 16; off <<= 1) {
#pragma unroll
            for (int j = 0; j < 8; j++)
                acc[j] += __shfl_xor_sync(0xffffffffu, acc[j], off);
        }

        // self loop
        {
            uint4 r0 = *(const uint4*)(pc + (size_t)n * 16 + q * 4);
            float2 f;
            f = __half22float2(*(__half2*)&r0.x); acc[0] += f.x; acc[1] += f.y;
            f = __half22float2(*(__half2*)&r0.y); acc[2] += f.x; acc[3] += f.y;
            f = __half22float2(*(__half2*)&r0.z); acc[4] += f.x; acc[5] += f.y;
            f = __half22float2(*(__half2*)&r0.w); acc[6] += f.x; acc[7] += f.y;
        }

        if (gslot == 0) {
            float inv = 1.0f / (1.0f + (float)(end - beg));
            uint4 praw;
            __half2 t0 = __floats2half2_rn(acc[0] * inv, acc[1] * inv);
            __half2 t1 = __floats2half2_rn(acc[2] * inv, acc[3] * inv);
            __half2 t2 = __floats2half2_rn(acc[4] * inv, acc[5] * inv);
            __half2 t3 = __floats2half2_rn(acc[6] * inv, acc[7] * inv);
            praw.x = *(uint32_t*)&t0; praw.y = *(uint32_t*)&t1;
            praw.z = *(uint32_t*)&t2; praw.w = *(uint32_t*)&t3;
            *(uint4*)(pn + (size_t)n * 16 + q * 4) = praw;
        }
    }
}

// ---------------- final: out = log_softmax(gamma0*h0 + sum_k gamma_k*sqrt(deg1)*p_k) ----------------
__global__ void k_out(const float* __restrict__ gamma, float* __restrict__ out) {
    __shared__ float gs[KSTEPS + 1];
    int tid = threadIdx.x;
    if (tid <= KSTEPS) gs[tid] = gamma[tid];
    __syncthreads();

    const int NW = 6250 * 8;
    int gw = blockIdx.x * 8 + (tid >> 5);
    int lane = tid & 31;

    for (int n = gw; n < N_NODES; n += NW) {
        float sq = sqrtf(1.0f + (float)(g_rowptr[n + 1] - g_rowptr[n]));
        size_t o = (size_t)n * N_CLS + lane;
        float v = gs[0] * g_h0[o];
#pragma unroll
        for (int k = 1; k <= KSTEPS; k++)
            v += gs[k] * sq * __half2float(((const __half*)g_ps[k])[o]);

        float m = v;
#pragma unroll
        for (int off = 16; off; off >>= 1)
            m = fmaxf(m, __shfl_xor_sync(0xffffffffu, m, off));
        float e = expf(v - m);
        float sum = e;
#pragma unroll
        for (int off = 16; off; off >>= 1)
            sum += __shfl_xor_sync(0xffffffffu, sum, off);
        out[o] = v - m - logf(sum);
    }
}

// ---------------- launch ----------------
extern "C" void kernel_launch(void* const* d_in, const int* in_sizes, int n_in,
                              void* d_out, int out_size) {
    const float* x     = (const float*)d_in[0];
    const void*  eiraw = d_in[1];
    const float* W1    = (const float*)d_in[2];
    const float* b1    = (const float*)d_in[3];
    const float* W2    = (const float*)d_in[4];
    const float* b2    = (const float*)d_in[5];
    const float* gamma = (const float*)d_in[6];
    float*       out   = (float*)d_out;

    // fork a side stream for the (independent) MLP chain
    cudaStream_t s2;
    cudaStreamCreateWithFlags(&s2, cudaStreamNonBlocking);
    cudaEvent_t eFork, eJoin;
    cudaEventCreateWithFlags(&eFork, cudaEventDisableTiming);
    cudaEventCreateWithFlags(&eJoin, cudaEventDisableTiming);

    cudaEventRecord(eFork, 0);
    cudaStreamWaitEvent(s2, eFork, 0);

    // side stream: weight conversion + MLP
    k_w1cvt<<<(F_IN * HID + 255) / 256, 256, 0, s2>>>(W1);
    k_w2cvt<<<(HID * N_CLS + 255) / 256, 256, 0, s2>>>(W2);
    cudaFuncSetAttribute(k_mlp, cudaFuncAttributeMaxDynamicSharedMemorySize, SMEM_T);
    k_mlp<<<(N_NODES + 127) / 128, 256, SMEM_T, s2>>>(x, b1, b2);
    cudaEventRecord(eJoin, s2);

    // main stream: edge preprocessing (raw edge list read directly)
    k_deg_zero<<<NBLK, 256>>>();
    k_sniff<<<1, 1>>>((const unsigned*)eiraw);
    k_degcnt<<<(N_EDGES + 255) / 256, 256>>>(eiraw);
    k_scan1<<<NBLK, 256>>>();
    k_scan2<<<1, 512>>>();
    k_scan3<<<NBLK, 256>>>();
    k_fill<<<(N_EDGES + 255) / 256, 256>>>(eiraw);

    // join: MLP results needed from here on
    cudaStreamWaitEvent(0, eJoin, 0);
    k_scale<<<(N_NODES * 16 + 255) / 256, 256>>>();

    for (int k = 1; k <= KSTEPS; k++)
        k_spmv<<<SPMV_BLOCKS, 256>>>(k);

    k_out<<<6250, 256>>>(gamma, out);
}

// round 16
// speedup vs baseline: 1.0475x; 1.0475x over previous
#include <cuda_runtime.h>
#include <cuda_bf16.h>
#include <cuda_fp16.h>
#include <cstdint>

#define N_NODES 100000
#define F_IN    512
#define HID     256
#define N_CLS   32
#define N_EDGES 3200000
#define KSTEPS  10
#define NBLK    ((N_NODES + 255) / 256)   // 391
#define SPMV_BLOCKS 6250                  // 2 nodes per warp (R14 optimum)

// ---------------- device scratch ----------------
__device__ __align__(128) float   g_h0[(size_t)N_NODES * N_CLS];          // fp32 h0 from MLP
__device__ __align__(128) __half2 g_ps[KSTEPS + 1][(size_t)N_NODES * 16]; // p_k history (fp16)
__device__ __align__(128) int     g_deg[N_NODES];
__device__ __align__(128) int     g_rowptr[N_NODES + 1];
__device__ __align__(128) int     g_pos[N_NODES];
__device__ __align__(128) int     g_csr_idx[N_EDGES];
__device__ __align__(128) int     g_bsum[512];
__device__ __align__(128) int     g_boff[512];
__device__ __align__(128) __nv_bfloat16 g_w1t_hi[(size_t)HID * F_IN];
__device__ __align__(128) __nv_bfloat16 g_w1t_lo[(size_t)HID * F_IN];
__device__ __align__(128) __nv_bfloat16 g_w2t_hi[(size_t)N_CLS * HID];
__device__ __align__(128) __nv_bfloat16 g_w2t_lo[(size_t)N_CLS * HID];
__device__ int g_is64;

// ---------------- edge index dtype sniff ----------------
__global__ void k_sniff(const unsigned* __restrict__ raw) {
    unsigned orv = 0;
#pragma unroll
    for (int i = 0; i < 16; i++) orv |= raw[2 * i + 1];
    g_is64 = (orv == 0u) ? 1 : 0;
}

__device__ __forceinline__ int edge_at(const void* raw, size_t idx) {
    return g_is64 ? (int)((const long long*)raw)[idx] : ((const int*)raw)[idx];
}

__global__ void k_degcnt(const void* __restrict__ raw) {
    int e = blockIdx.x * blockDim.x + threadIdx.x;
    if (e < N_EDGES) atomicAdd(&g_deg[edge_at(raw, (size_t)N_EDGES + e)], 1);
}

__global__ void k_deg_zero() {
    int i = blockIdx.x * blockDim.x + threadIdx.x;
    if (i < N_NODES) g_deg[i] = 0;
}

// ---------------- parallel exclusive scan of g_deg -> g_rowptr/g_pos ----------------
__global__ __launch_bounds__(256) void k_scan1() {
    __shared__ int wsum[8];
    int tid = threadIdx.x;
    int i = blockIdx.x * 256 + tid;
    int v = (i < N_NODES) ? g_deg[i] : 0;
    int x = v;
#pragma unroll
    for (int o = 16; o; o >>= 1) x += __shfl_down_sync(0xffffffffu, x, o);
    if ((tid & 31) == 0) wsum[tid >> 5] = x;
    __syncthreads();
    if (tid < 8) {
        int y = wsum[tid];
#pragma unroll
        for (int o = 4; o; o >>= 1) y += __shfl_down_sync(0xffu, y, o);
        if (tid == 0) g_bsum[blockIdx.x] = y;
    }
}

__global__ __launch_bounds__(512) void k_scan2() {
    __shared__ int wsum[16];
    int tid = threadIdx.x;
    int lane = tid & 31, w = tid >> 5;
    int v = (tid < NBLK) ? g_bsum[tid] : 0;
    int x = v;
#pragma unroll
    for (int o = 1; o < 32; o <<= 1) {
        int t = __shfl_up_sync(0xffffffffu, x, o);
        if (lane >= o) x += t;
    }
    if (lane == 31) wsum[w] = x;
    __syncthreads();
    if (tid < 16) {
        int y = wsum[tid];
#pragma unroll
        for (int o = 1; o < 16; o <<= 1) {
            int t = __shfl_up_sync(0xffffu, y, o);
            if (tid >= o) y += t;
        }
        wsum[tid] = y;
    }
    __syncthreads();
    int pre = (w > 0) ? wsum[w - 1] : 0;
    int excl = pre + x - v;
    g_boff[tid] = excl;
    if (tid == NBLK) g_rowptr[N_NODES] = excl;
}

__global__ __launch_bounds__(256) void k_scan3() {
    __shared__ int wsum[8];
    int tid = threadIdx.x;
    int i = blockIdx.x * 256 + tid;
    int lane = tid & 31, w = tid >> 5;
    int v = (i < N_NODES) ? g_deg[i] : 0;
    int x = v;
#pragma unroll
    for (int o = 1; o < 32; o <<= 1) {
        int t = __shfl_up_sync(0xffffffffu, x, o);
        if (lane >= o) x += t;
    }
    if (lane == 31) wsum[w] = x;
    __syncthreads();
    if (tid < 8) {
        int y = wsum[tid];
#pragma unroll
        for (int o = 1; o < 8; o <<= 1) {
            int t = __shfl_up_sync(0xffu, y, o);
            if (tid >= o) y += t;
        }
        wsum[tid] = y;
    }
    __syncthreads();
    int pre = (w > 0) ? wsum[w - 1] : 0;
    int excl = g_boff[blockIdx.x] + pre + x - v;
    if (i < N_NODES) { g_rowptr[i] = excl; g_pos[i] = excl; }
}

__global__ void k_fill(const void* __restrict__ raw) {
    int e = blockIdx.x * blockDim.x + threadIdx.x;
    if (e >= N_EDGES) return;
    int s = edge_at(raw, e);
    int d = edge_at(raw, (size_t)N_EDGES + e);
    int p = atomicAdd(&g_pos[d], 1);
    g_csr_idx[p] = s;
}

// ---------------- weight conversions ----------------
__global__ void k_w1cvt(const float* __restrict__ W1) {
    int i = blockIdx.x * blockDim.x + threadIdx.x;
    if (i >= F_IN * HID) return;
    int k = i / HID, n = i % HID;
    float v = W1[i];
    __nv_bfloat16 h = __float2bfloat16(v);
    g_w1t_hi[(size_t)n * F_IN + k] = h;
    g_w1t_lo[(size_t)n * F_IN + k] = __float2bfloat16(v - __bfloat162float(h));
}

__global__ void k_w2cvt(const float* __restrict__ W2) {
    int i = blockIdx.x * blockDim.x + threadIdx.x;
    if (i >= HID * N_CLS) return;
    int k = i / N_CLS, n = i % N_CLS;
    float v = W2[i];
    __nv_bfloat16 h = __float2bfloat16(v);
    g_w2t_hi[(size_t)n * HID + k] = h;
    g_w2t_lo[(size_t)n * HID + k] = __float2bfloat16(v - __bfloat162float(h));
}

// ---------------- fused MLP: h0 = relu(x@W1+b1)@W2 + b2 ----------------
#define ST1  72
#define ST2  264

#define ASH_O   0u
#define ASL_O   18432u
#define BSH_O   36864u
#define BSL_O   73728u
#define ZHI_O   0u
#define ZLO_O   67584u
#define W2HI_O  135168u
#define W2LO_O  152064u
#define B2_O    168960u
#define BIAS_O  169088u
#define SMEM_T  170112u

#define MMA16816(c, a, b) \
    asm volatile("mma.sync.aligned.m16n8k16.row.col.f32.bf16.bf16.f32 " \
                 "{%0,%1,%2,%3},{%4,%5,%6,%7},{%8,%9},{%0,%1,%2,%3};" \
                 : "+f"((c)[0]), "+f"((c)[1]), "+f"((c)[2]), "+f"((c)[3]) \
                 : "r"((a)[0]), "r"((a)[1]), "r"((a)[2]), "r"((a)[3]), \
                   "r"((b)[0]), "r"((b)[1]))

#define LDSM4(r, a) \
    asm volatile("ldmatrix.sync.aligned.m8n8.x4.shared.b16 {%0,%1,%2,%3}, [%4];" \
                 : "=r"((r)[0]), "=r"((r)[1]), "=r"((r)[2]), "=r"((r)[3]) : "r"(a))

#define LDSM2(r, a) \
    asm volatile("ldmatrix.sync.aligned.m8n8.x2.shared.b16 {%0,%1}, [%2];" \
                 : "=r"((r)[0]), "=r"((r)[1]) : "r"(a))

__device__ __forceinline__ uint32_t pack_hi(float a, float b) {
    __nv_bfloat16 h0 = __float2bfloat16(a), h1 = __float2bfloat16(b);
    return (uint32_t)__bfloat16_as_ushort(h0) | ((uint32_t)__bfloat16_as_ushort(h1) << 16);
}
__device__ __forceinline__ uint32_t pack_lo(float a, float b) {
    __nv_bfloat16 h0 = __float2bfloat16(a), h1 = __float2bfloat16(b);
    float r0 = a - __bfloat162float(h0), r1 = b - __bfloat162float(h1);
    __nv_bfloat16 l0 = __float2bfloat16(r0), l1 = __float2bfloat16(r1);
    return (uint32_t)__bfloat16_as_ushort(l0) | ((uint32_t)__bfloat16_as_ushort(l1) << 16);
}

__global__ __launch_bounds__(256, 1) void k_mlp(const float* __restrict__ x,
                                                const float* __restrict__ b1,
                                                const float* __restrict__ b2) {
    extern __shared__ __align__(16) char sm[];
    __nv_bfloat16* as_hi = (__nv_bfloat16*)(sm + ASH_O);
    __nv_bfloat16* as_lo = (__nv_bfloat16*)(sm + ASL_O);
    __nv_bfloat16* bs_hi = (__nv_bfloat16*)(sm + BSH_O);
    __nv_bfloat16* bs_lo = (__nv_bfloat16*)(sm + BSL_O);
    uint32_t* zhi = (uint32_t*)(sm + ZHI_O);
    uint32_t* zlo = (uint32_t*)(sm + ZLO_O);
    __nv_bfloat16* w2hi = (__nv_bfloat16*)(sm + W2HI_O);
    __nv_bfloat16* w2lo = (__nv_bfloat16*)(sm + W2LO_O);
    float* b2s = (float*)(sm + B2_O);
    float* bias_s = (float*)(sm + BIAS_O);

    const int tid = threadIdx.x;
    const int wid = tid >> 5, lane = tid & 31;
    const int gq = lane >> 2, tg = lane & 3;
    const int rowBase = blockIdx.x * 128;
    const int wr = (wid >> 2) * 64, wc = (wid & 3) * 64;

    bias_s[tid] = b1[tid];
    if (tid < N_CLS) b2s[tid] = b2[tid];
    for (int i = tid; i < 1024; i += 256) {
        int n = i >> 5, k8 = (i & 31) * 8;
        *(uint4*)(w2hi + n * ST2 + k8) = *(const uint4*)(g_w2t_hi + n * HID + k8);
        *(uint4*)(w2lo + n * ST2 + k8) = *(const uint4*)(g_w2t_lo + n * HID + k8);
    }

    float acc[4][8][4];
#pragma unroll
    for (int a = 0; a < 4; a++)
#pragma unroll
        for (int b = 0; b < 8; b++)
#pragma unroll
            for (int c = 0; c < 4; c++) acc[a][b][c] = 0.f;

    // ldmatrix lane-address precomputation (phase 1)
    const uint32_t ash_b = (uint32_t)__cvta_generic_to_shared(as_hi);
    const uint32_t asl_b = (uint32_t)__cvta_generic_to_shared(as_lo);
    const uint32_t bsh_b = (uint32_t)__cvta_generic_to_shared(bs_hi);
    const uint32_t bsl_b = (uint32_t)__cvta_generic_to_shared(bs_lo);
    const int am = lane >> 3;                              // matrix id 0..3
    const int aoff_row = (lane & 7) + ((am & 1) << 3);     // +8 rows for m1,m3
    const int aoff_k = (am >> 1) << 3;                     // +8 k for m2,m3
    int aRow[4];
#pragma unroll
    for (int mt = 0; mt < 4; mt++)
        aRow[mt] = (wr + mt * 16 + aoff_row) * ST1;
    const int blx = lane & 15;
    const int boff_row = blx & 7;
    const int boff_k = (blx >> 3) << 3;

    float4 aPre[8];
    {
#pragma unroll
        for (int j = 0; j < 8; j++) {
            int i = tid + 256 * j;
            int r = i >> 4, cc = (i & 15) * 4;
            int grow = rowBase + r;
            aPre[j] = make_float4(0.f, 0.f, 0.f, 0.f);
            if (grow < N_NODES)
                aPre[j] = *(const float4*)(x + (size_t)grow * F_IN + cc);
        }
    }

    for (int ch = 0; ch < 8; ch++) {
        const int k0 = ch * 64;
        __syncthreads();
#pragma unroll
        for (int j = 0; j < 8; j++) {
            int i = tid + 256 * j;
            int r = i >> 4, cc = (i & 15) * 4;
            float4 v = aPre[j];
            uint2 ph = make_uint2(pack_hi(v.x, v.y), pack_hi(v.z, v.w));
            uint2 pl = make_uint2(pack_lo(v.x, v.y), pack_lo(v.z, v.w));
            *(uint2*)(as_hi + r * ST1 + cc) = ph;
            *(uint2*)(as_lo + r * ST1 + cc) = pl;
        }
        for (int i = tid; i < 2048; i += 256) {
            int n = i >> 3, k8 = (i & 7) * 8;
            size_t gi = (size_t)n * F_IN + k0 + k8;
            *(uint4*)(bs_hi + n * ST1 + k8) = *(const uint4*)(g_w1t_hi + gi);
            *(uint4*)(bs_lo + n * ST1 + k8) = *(const uint4*)(g_w1t_lo + gi);
        }
        __syncthreads();

        if (ch < 7) {
            const int k1 = (ch + 1) * 64;
#pragma unroll
            for (int j = 0; j < 8; j++) {
                int i = tid + 256 * j;
                int r = i >> 4, cc = (i & 15) * 4;
                int grow = rowBase + r;
                aPre[j] = make_float4(0.f, 0.f, 0.f, 0.f);
                if (grow < N_NODES)
                    aPre[j] = *(const float4*)(x + (size_t)grow * F_IN + k1 + cc);
            }
        }

#pragma unroll
        for (int ks = 0; ks < 4; ks++) {
            const int ko = ks * 16;
            uint32_t ah[4][4], al[4][4];
#pragma unroll
            for (int mt = 0; mt < 4; mt++) {
                uint32_t off = (uint32_t)(aRow[mt] + ko + aoff_k) * 2u;
                LDSM4(ah[mt], ash_b + off);
                LDSM4(al[mt], asl_b + off);
            }
#pragma unroll
            for (int nt = 0; nt < 8; nt++) {
                uint32_t boff = (uint32_t)((wc + nt * 8 + boff_row) * ST1 + ko + boff_k) * 2u;
                uint32_t bh[2], bl[2];
                LDSM2(bh, bsh_b + boff);
                LDSM2(bl, bsl_b + boff);
#pragma unroll
                for (int mt = 0; mt < 4; mt++) {
                    MMA16816(acc[mt][nt], ah[mt], bh);
                    MMA16816(acc[mt][nt], ah[mt], bl);
                    MMA16816(acc[mt][nt], al[mt], bh);
                }
            }
        }
    }

    __syncthreads();

#pragma unroll
    for (int mt = 0; mt < 4; mt++) {
        int r0 = wr + mt * 16 + gq;
        int r1 = r0 + 8;
#pragma unroll
        for (int nt = 0; nt < 8; nt++) {
            int cl = wc + nt * 8 + 2 * tg;
            float bx = bias_s[cl], by = bias_s[cl + 1];
            float o0 = fmaxf(acc[mt][nt][0] + bx, 0.f);
            float o1 = fmaxf(acc[mt][nt][1] + by, 0.f);
            float o2 = fmaxf(acc[mt][nt][2] + bx, 0.f);
            float o3 = fmaxf(acc[mt][nt][3] + by, 0.f);
            int w0 = r0 * 132 + (cl >> 1);
            int w1 = r1 * 132 + (cl >> 1);
            zhi[w0] = pack_hi(o0, o1); zlo[w0] = pack_lo(o0, o1);
            zhi[w1] = pack_hi(o2, o3); zlo[w1] = pack_lo(o2, o3);
        }
    }
    __syncthreads();

    float acc2[4][4];
#pragma unroll
    for (int a = 0; a < 4; a++)
#pragma unroll
        for (int c = 0; c < 4; c++) acc2[a][c] = 0.f;

    const int rl0 = wid * 16 + gq;
#pragma unroll
    for (int ks = 0; ks < 16; ks++) {
        const int kw = ks * 8 + tg;
        uint32_t ah[4], al[4];
        ah[0] = zhi[rl0 * 132 + kw];
        ah[1] = zhi[(rl0 + 8) * 132 + kw];
        ah[2] = zhi[rl0 * 132 + kw + 4];
        ah[3] = zhi[(rl0 + 8) * 132 + kw + 4];
        al[0] = zlo[rl0 * 132 + kw];
        al[1] = zlo[(rl0 + 8) * 132 + kw];
        al[2] = zlo[rl0 * 132 + kw + 4];
        al[3] = zlo[(rl0 + 8) * 132 + kw + 4];
#pragma unroll
        for (int nt = 0; nt < 4; nt++) {
            int n0 = nt * 8 + gq;
            uint32_t bh[2], bl[2];
            bh[0] = *(const uint32_t*)(w2hi + n0 * ST2 + ks * 16 + 2 * tg);
            bh[1] = *(const uint32_t*)(w2hi + n0 * ST2 + ks * 16 + 8 + 2 * tg);
            bl[0] = *(const uint32_t*)(w2lo + n0 * ST2 + ks * 16 + 2 * tg);
            bl[1] = *(const uint32_t*)(w2lo + n0 * ST2 + ks * 16 + 8 + 2 * tg);
            MMA16816(acc2[nt], ah, bh);
            MMA16816(acc2[nt], ah, bl);
            MMA16816(acc2[nt], al, bh);
        }
    }

    int row0 = rowBase + rl0, row1 = row0 + 8;
#pragma unroll
    for (int nt = 0; nt < 4; nt++) {
        int cl = nt * 8 + 2 * tg;
        float bx = b2s[cl], by = b2s[cl + 1];
        if (row0 < N_NODES)
            *(float2*)(g_h0 + (size_t)row0 * N_CLS + cl) =
                make_float2(acc2[nt][0] + bx, acc2[nt][1] + by);
        if (row1 < N_NODES)
            *(float2*)(g_h0 + (size_t)row1 * N_CLS + cl) =
                make_float2(acc2[nt][2] + bx, acc2[nt][3] + by);
    }
}

// ---------------- scale: p_0 = fp16(dinv * h0) ----------------
__global__ void k_scale() {
    int i = blockIdx.x * blockDim.x + threadIdx.x;   // one half2 (2 classes)
    if (i >= N_NODES * 16) return;
    int n = i >> 4;
    float di = rsqrtf(1.0f + (float)g_deg[n]);
    float2 v = *(float2*)(g_h0 + (size_t)i * 2);
    g_ps[0][i] = __floats2half2_rn(v.x * di, v.y * di);
}

// ---------------- SpMV step: p_k = A_norm * p_{k-1} (2 nodes per warp) ----------------
// 4 lanes per edge; lane q = lane&3 owns classes [8q, 8q+8); gslot = lane>>2
__global__ __launch_bounds__(256) void k_spmv(int kidx) {
    const __half2* __restrict__ pc = g_ps[kidx - 1];
    __half2* __restrict__ pn = g_ps[kidx];

    const int NW = SPMV_BLOCKS * 8;   // total warps = 50000
    const int gw = blockIdx.x * 8 + (threadIdx.x >> 5);
    const int lane = threadIdx.x & 31;
    const int q = lane & 3;
    const int gslot = lane >> 2;

    for (int n = gw; n < N_NODES; n += NW) {
        int beg = g_rowptr[n], end = g_rowptr[n + 1];

        float acc[8];
#pragma unroll
        for (int j = 0; j < 8; j++) acc[j] = 0.f;

        int e = beg;
        for (; e + 16 <= end; e += 16) {
            int s0 = g_csr_idx[e + gslot];
            int s1 = g_csr_idx[e + 8 + gslot];
            uint4 r0 = *(const uint4*)(pc + (size_t)s0 * 16 + q * 4);
            uint4 r1 = *(const uint4*)(pc + (size_t)s1 * 16 + q * 4);
            float2 f;
            f = __half22float2(*(__half2*)&r0.x); acc[0] += f.x; acc[1] += f.y;
            f = __half22float2(*(__half2*)&r0.y); acc[2] += f.x; acc[3] += f.y;
            f = __half22float2(*(__half2*)&r0.z); acc[4] += f.x; acc[5] += f.y;
            f = __half22float2(*(__half2*)&r0.w); acc[6] += f.x; acc[7] += f.y;
            f = __half22float2(*(__half2*)&r1.x); acc[0] += f.x; acc[1] += f.y;
            f = __half22float2(*(__half2*)&r1.y); acc[2] += f.x; acc[3] += f.y;
            f = __half22float2(*(__half2*)&r1.z); acc[4] += f.x; acc[5] += f.y;
            f = __half22float2(*(__half2*)&r1.w); acc[6] += f.x; acc[7] += f.y;
        }
        for (; e < end; e += 8) {
            int ee = e + gslot;
            if (ee < end) {
                int s = g_csr_idx[ee];
                uint4 r0 = *(const uint4*)(pc + (size_t)s * 16 + q * 4);
                float2 f;
                f = __half22float2(*(__half2*)&r0.x); acc[0] += f.x; acc[1] += f.y;
                f = __half22float2(*(__half2*)&r0.y); acc[2] += f.x; acc[3] += f.y;
                f = __half22float2(*(__half2*)&r0.z); acc[4] += f.x; acc[5] += f.y;
                f = __half22float2(*(__half2*)&r0.w); acc[6] += f.x; acc[7] += f.y;
            }
        }

#pragma unroll
        for (int off = 4; off <= 16; off <<= 1) {
#pragma unroll
            for (int j = 0; j < 8; j++)
                acc[j] += __shfl_xor_sync(0xffffffffu, acc[j], off);
        }

        // self loop
        {
            uint4 r0 = *(const uint4*)(pc + (size_t)n * 16 + q * 4);
            float2 f;
            f = __half22float2(*(__half2*)&r0.x); acc[0] += f.x; acc[1] += f.y;
            f = __half22float2(*(__half2*)&r0.y); acc[2] += f.x; acc[3] += f.y;
            f = __half22float2(*(__half2*)&r0.z); acc[4] += f.x; acc[5] += f.y;
            f = __half22float2(*(__half2*)&r0.w); acc[6] += f.x; acc[7] += f.y;
        }

        if (gslot == 0) {
            float inv = 1.0f / (1.0f + (float)(end - beg));
            uint4 praw;
            __half2 t0 = __floats2half2_rn(acc[0] * inv, acc[1] * inv);
            __half2 t1 = __floats2half2_rn(acc[2] * inv, acc[3] * inv);
            __half2 t2 = __floats2half2_rn(acc[4] * inv, acc[5] * inv);
            __half2 t3 = __floats2half2_rn(acc[6] * inv, acc[7] * inv);
            praw.x = *(uint32_t*)&t0; praw.y = *(uint32_t*)&t1;
            praw.z = *(uint32_t*)&t2; praw.w = *(uint32_t*)&t3;
            *(uint4*)(pn + (size_t)n * 16 + q * 4) = praw;
        }
    }
}

// ---------------- final: out = log_softmax(gamma0*h0 + sum_k gamma_k*sqrt(deg1)*p_k) ----------------
__global__ void k_out(const float* __restrict__ gamma, float* __restrict__ out) {
    __shared__ float gs[KSTEPS + 1];
    int tid = threadIdx.x;
    if (tid <= KSTEPS) gs[tid] = gamma[tid];
    __syncthreads();

    int warp = tid >> 5, lane = tid & 31;
    int n = blockIdx.x * 8 + warp;
    if (n >= N_NODES) return;

    float sq = sqrtf(1.0f + (float)(g_rowptr[n + 1] - g_rowptr[n]));
    size_t o = (size_t)n * N_CLS + lane;
    float v = gs[0] * g_h0[o];
#pragma unroll
    for (int k = 1; k <= KSTEPS; k++)
        v += gs[k] * sq * __half2float(((const __half*)g_ps[k])[o]);

    float m = v;
#pragma unroll
    for (int off = 16; off; off >>= 1)
        m = fmaxf(m, __shfl_xor_sync(0xffffffffu, m, off));
    float e = expf(v - m);
    float sum = e;
#pragma unroll
    for (int off = 16; off; off >>= 1)
        sum += __shfl_xor_sync(0xffffffffu, sum, off);
    out[o] = v - m - logf(sum);
}

// ---------------- launch ----------------
extern "C" void kernel_launch(void* const* d_in, const int* in_sizes, int n_in,
                              void* d_out, int out_size) {
    const float* x     = (const float*)d_in[0];
    const void*  eiraw = d_in[1];
    const float* W1    = (const float*)d_in[2];
    const float* b1    = (const float*)d_in[3];
    const float* W2    = (const float*)d_in[4];
    const float* b2    = (const float*)d_in[5];
    const float* gamma = (const float*)d_in[6];
    float*       out   = (float*)d_out;

    // fork a side stream for the (independent) MLP chain
    cudaStream_t s2;
    cudaStreamCreateWithFlags(&s2, cudaStreamNonBlocking);
    cudaEvent_t eFork, eJoin;
    cudaEventCreateWithFlags(&eFork, cudaEventDisableTiming);
    cudaEventCreateWithFlags(&eJoin, cudaEventDisableTiming);

    cudaEventRecord(eFork, 0);
    cudaStreamWaitEvent(s2, eFork, 0);

    // side stream: weight conversion + MLP
    k_w1cvt<<<(F_IN * HID + 255) / 256, 256, 0, s2>>>(W1);
    k_w2cvt<<<(HID * N_CLS + 255) / 256, 256, 0, s2>>>(W2);
    cudaFuncSetAttribute(k_mlp, cudaFuncAttributeMaxDynamicSharedMemorySize, SMEM_T);
    k_mlp<<<(N_NODES + 127) / 128, 256, SMEM_T, s2>>>(x, b1, b2);
    cudaEventRecord(eJoin, s2);

    // main stream: edge preprocessing (raw edge list read directly)
    k_deg_zero<<<NBLK, 256>>>();
    k_sniff<<<1, 1>>>((const unsigned*)eiraw);
    k_degcnt<<<(N_EDGES + 255) / 256, 256>>>(eiraw);
    k_scan1<<<NBLK, 256>>>();
    k_scan2<<<1, 512>>>();
    k_scan3<<<NBLK, 256>>>();
    k_fill<<<(N_EDGES + 255) / 256, 256>>>(eiraw);

    // join: MLP results needed from here on
    cudaStreamWaitEvent(0, eJoin, 0);
    k_scale<<<(N_NODES * 16 + 255) / 256, 256>>>();

    for (int k = 1; k <= KSTEPS; k++)
        k_spmv<<<SPMV_BLOCKS, 256>>>(k);

    k_out<<<(N_NODES + 7) / 8, 256>>>(gamma, out);
}

// round 17
// speedup vs baseline: 1.1458x; 1.0938x over previous
#include <cuda_runtime.h>
#include <cuda_bf16.h>
#include <cuda_fp16.h>
#include <cstdint>

#define N_NODES 100000
#define F_IN    512
#define HID     256
#define N_CLS   32
#define N_EDGES 3200000
#define KSTEPS  10
#define NBLK    ((N_NODES + 255) / 256)   // 391
#define SPMV_BLOCKS 6250                  // 2 nodes per warp (R14 optimum)

// ---------------- device scratch ----------------
__device__ __align__(128) float   g_h0[(size_t)N_NODES * N_CLS];          // fp32 h0 from MLP
__device__ __align__(128) __half2 g_ps[KSTEPS + 1][(size_t)N_NODES * 16]; // p_k history (fp16)
__device__ __align__(128) int     g_deg[N_NODES];
__device__ __align__(128) int     g_rowptr[N_NODES + 1];
__device__ __align__(128) int     g_pos[N_NODES];
__device__ __align__(128) int     g_csr_idx[N_EDGES];
__device__ __align__(128) int     g_bsum[512];
__device__ __align__(128) int     g_boff[512];
__device__ __align__(128) uint32_t g_w1t[(size_t)HID * F_IN];   // tf32 bits, transposed [n][k]
__device__ __align__(128) uint32_t g_w2t[(size_t)N_CLS * HID];  // tf32 bits, [n][k]
__device__ int g_is64;

__device__ __forceinline__ uint32_t tf32r(float v) {
    uint32_t t;
    asm("cvt.rna.tf32.f32 %0, %1;" : "=r"(t) : "f"(v));
    return t;
}

// ---------------- edge index dtype sniff ----------------
__global__ void k_sniff(const unsigned* __restrict__ raw) {
    unsigned orv = 0;
#pragma unroll
    for (int i = 0; i < 16; i++) orv |= raw[2 * i + 1];
    g_is64 = (orv == 0u) ? 1 : 0;
}

__device__ __forceinline__ int edge_at(const void* raw, size_t idx) {
    return g_is64 ? (int)((const long long*)raw)[idx] : ((const int*)raw)[idx];
}

__global__ void k_degcnt(const void* __restrict__ raw) {
    int e = blockIdx.x * blockDim.x + threadIdx.x;
    if (e < N_EDGES) atomicAdd(&g_deg[edge_at(raw, (size_t)N_EDGES + e)], 1);
}

__global__ void k_deg_zero() {
    int i = blockIdx.x * blockDim.x + threadIdx.x;
    if (i < N_NODES) g_deg[i] = 0;
}

// ---------------- parallel exclusive scan of g_deg -> g_rowptr/g_pos ----------------
__global__ __launch_bounds__(256) void k_scan1() {
    __shared__ int wsum[8];
    int tid = threadIdx.x;
    int i = blockIdx.x * 256 + tid;
    int v = (i < N_NODES) ? g_deg[i] : 0;
    int x = v;
#pragma unroll
    for (int o = 16; o; o >>= 1) x += __shfl_down_sync(0xffffffffu, x, o);
    if ((tid & 31) == 0) wsum[tid >> 5] = x;
    __syncthreads();
    if (tid < 8) {
        int y = wsum[tid];
#pragma unroll
        for (int o = 4; o; o >>= 1) y += __shfl_down_sync(0xffu, y, o);
        if (tid == 0) g_bsum[blockIdx.x] = y;
    }
}

__global__ __launch_bounds__(512) void k_scan2() {
    __shared__ int wsum[16];
    int tid = threadIdx.x;
    int lane = tid & 31, w = tid >> 5;
    int v = (tid < NBLK) ? g_bsum[tid] : 0;
    int x = v;
#pragma unroll
    for (int o = 1; o < 32; o <<= 1) {
        int t = __shfl_up_sync(0xffffffffu, x, o);
        if (lane >= o) x += t;
    }
    if (lane == 31) wsum[w] = x;
    __syncthreads();
    if (tid < 16) {
        int y = wsum[tid];
#pragma unroll
        for (int o = 1; o < 16; o <<= 1) {
            int t = __shfl_up_sync(0xffffu, y, o);
            if (tid >= o) y += t;
        }
        wsum[tid] = y;
    }
    __syncthreads();
    int pre = (w > 0) ? wsum[w - 1] : 0;
    int excl = pre + x - v;
    g_boff[tid] = excl;
    if (tid == NBLK) g_rowptr[N_NODES] = excl;
}

__global__ __launch_bounds__(256) void k_scan3() {
    __shared__ int wsum[8];
    int tid = threadIdx.x;
    int i = blockIdx.x * 256 + tid;
    int lane = tid & 31, w = tid >> 5;
    int v = (i < N_NODES) ? g_deg[i] : 0;
    int x = v;
#pragma unroll
    for (int o = 1; o < 32; o <<= 1) {
        int t = __shfl_up_sync(0xffffffffu, x, o);
        if (lane >= o) x += t;
    }
    if (lane == 31) wsum[w] = x;
    __syncthreads();
    if (tid < 8) {
        int y = wsum[tid];
#pragma unroll
        for (int o = 1; o < 8; o <<= 1) {
            int t = __shfl_up_sync(0xffu, y, o);
            if (tid >= o) y += t;
        }
        wsum[tid] = y;
    }
    __syncthreads();
    int pre = (w > 0) ? wsum[w - 1] : 0;
    int excl = g_boff[blockIdx.x] + pre + x - v;
    if (i < N_NODES) { g_rowptr[i] = excl; g_pos[i] = excl; }
}

__global__ void k_fill(const void* __restrict__ raw) {
    int e = blockIdx.x * blockDim.x + threadIdx.x;
    if (e >= N_EDGES) return;
    int s = edge_at(raw, e);
    int d = edge_at(raw, (size_t)N_EDGES + e);
    int p = atomicAdd(&g_pos[d], 1);
    g_csr_idx[p] = s;
}

// ---------------- weight conversions (fp32 -> tf32 bits) ----------------
__global__ void k_w1cvt(const float* __restrict__ W1) {
    int i = blockIdx.x * blockDim.x + threadIdx.x;
    if (i >= F_IN * HID) return;
    int k = i / HID, n = i % HID;
    g_w1t[(size_t)n * F_IN + k] = tf32r(W1[i]);
}

__global__ void k_w2cvt(const float* __restrict__ W2) {
    int i = blockIdx.x * blockDim.x + threadIdx.x;
    if (i >= HID * N_CLS) return;
    int k = i / N_CLS, n = i % N_CLS;
    g_w2t[(size_t)n * HID + k] = tf32r(W2[i]);
}

// ---------------- fused MLP (TF32): h0 = relu(x@W1+b1)@W2 + b2 ----------------
#define ST1F  68     // phase1 smem stride (floats)
#define STZF  260    // z stride (floats)
#define STWF  268    // W2 stride (floats)

#define A_O     0u         // 128*68*4  = 34816
#define B_O     34816u     // 256*68*4  = 69632 -> 104448
#define Z_O     0u         // 128*260*4 = 133120
#define W2_O    133120u    // 32*268*4  = 34304 -> 167424
#define BIAS_O  167424u    // 1024
#define B2_O    168448u    // 128
#define SMEM_T  168576u

#define MMATF32(c, a, b) \
    asm volatile("mma.sync.aligned.m16n8k8.row.col.f32.tf32.tf32.f32 " \
                 "{%0,%1,%2,%3},{%4,%5,%6,%7},{%8,%9},{%0,%1,%2,%3};" \
                 : "+f"((c)[0]), "+f"((c)[1]), "+f"((c)[2]), "+f"((c)[3]) \
                 : "r"((a)[0]), "r"((a)[1]), "r"((a)[2]), "r"((a)[3]), \
                   "r"((b)[0]), "r"((b)[1]))

__global__ __launch_bounds__(256, 1) void k_mlp(const float* __restrict__ x,
                                                const float* __restrict__ b1,
                                                const float* __restrict__ b2) {
    extern __shared__ __align__(16) char sm[];
    uint32_t* As = (uint32_t*)(sm + A_O);
    uint32_t* Bs = (uint32_t*)(sm + B_O);
    uint32_t* Zs = (uint32_t*)(sm + Z_O);
    uint32_t* W2s = (uint32_t*)(sm + W2_O);
    float* bias_s = (float*)(sm + BIAS_O);
    float* b2s = (float*)(sm + B2_O);

    const int tid = threadIdx.x;
    const int wid = tid >> 5, lane = tid & 31;
    const int gq = lane >> 2, tg = lane & 3;
    const int rowBase = blockIdx.x * 128;
    const int wr = (wid >> 2) * 64, wc = (wid & 3) * 64;

    bias_s[tid] = b1[tid];
    if (tid < N_CLS) b2s[tid] = b2[tid];
    // W2 tf32 into smem: 32 rows x 256 k (2048 float4)
    for (int i = tid; i < 2048; i += 256) {
        int n = i >> 6, k4 = (i & 63) * 4;
        *(uint4*)(W2s + n * STWF + k4) = *(const uint4*)(g_w2t + n * HID + k4);
    }

    float acc[4][8][4];
#pragma unroll
    for (int a = 0; a < 4; a++)
#pragma unroll
        for (int b = 0; b < 8; b++)
#pragma unroll
            for (int c = 0; c < 4; c++) acc[a][b][c] = 0.f;

    float4 aPre[8];
    {
#pragma unroll
        for (int j = 0; j < 8; j++) {
            int i = tid + 256 * j;
            int r = i >> 4, cc = (i & 15) * 4;
            int grow = rowBase + r;
            aPre[j] = make_float4(0.f, 0.f, 0.f, 0.f);
            if (grow < N_NODES)
                aPre[j] = *(const float4*)(x + (size_t)grow * F_IN + cc);
        }
    }

    for (int ch = 0; ch < 8; ch++) {
        const int k0 = ch * 64;
        __syncthreads();
        // A tile 128x64: convert fp32 -> tf32 and store
#pragma unroll
        for (int j = 0; j < 8; j++) {
            int i = tid + 256 * j;
            int r = i >> 4, cc = (i & 15) * 4;
            float4 v = aPre[j];
            uint4 t;
            t.x = tf32r(v.x); t.y = tf32r(v.y); t.z = tf32r(v.z); t.w = tf32r(v.w);
            *(uint4*)(As + r * ST1F + cc) = t;
        }
        // B tile 256x64 (preconverted tf32)
        for (int i = tid; i < 4096; i += 256) {
            int n = i >> 4, k4 = (i & 15) * 4;
            *(uint4*)(Bs + n * ST1F + k4) = *(const uint4*)(g_w1t + (size_t)n * F_IN + k0 + k4);
        }
        __syncthreads();

        if (ch < 7) {
            const int k1 = (ch + 1) * 64;
#pragma unroll
            for (int j = 0; j < 8; j++) {
                int i = tid + 256 * j;
                int r = i >> 4, cc = (i & 15) * 4;
                int grow = rowBase + r;
                aPre[j] = make_float4(0.f, 0.f, 0.f, 0.f);
                if (grow < N_NODES)
                    aPre[j] = *(const float4*)(x + (size_t)grow * F_IN + k1 + cc);
            }
        }

#pragma unroll
        for (int ks = 0; ks < 8; ks++) {
            const int ko = ks * 8;
            uint32_t a[4][4];
#pragma unroll
            for (int mt = 0; mt < 4; mt++) {
                int r0 = wr + mt * 16 + gq;
                a[mt][0] = As[r0 * ST1F + ko + tg];
                a[mt][1] = As[(r0 + 8) * ST1F + ko + tg];
                a[mt][2] = As[r0 * ST1F + ko + 4 + tg];
                a[mt][3] = As[(r0 + 8) * ST1F + ko + 4 + tg];
            }
#pragma unroll
            for (int nt = 0; nt < 8; nt++) {
                int n0 = wc + nt * 8 + gq;
                uint32_t b[2];
                b[0] = Bs[n0 * ST1F + ko + tg];
                b[1] = Bs[n0 * ST1F + ko + 4 + tg];
#pragma unroll
                for (int mt = 0; mt < 4; mt++)
                    MMATF32(acc[mt][nt], a[mt], b);
            }
        }
    }

    __syncthreads();   // all phase-1 MMA done before smem reuse

    // phase1 epilogue: bias + relu -> tf32 z in smem
#pragma unroll
    for (int mt = 0; mt < 4; mt++) {
        int r0 = wr + mt * 16 + gq;
        int r1 = r0 + 8;
#pragma unroll
        for (int nt = 0; nt < 8; nt++) {
            int cl = wc + nt * 8 + 2 * tg;
            float bx = bias_s[cl], by = bias_s[cl + 1];
            Zs[r0 * STZF + cl]     = tf32r(fmaxf(acc[mt][nt][0] + bx, 0.f));
            Zs[r0 * STZF + cl + 1] = tf32r(fmaxf(acc[mt][nt][1] + by, 0.f));
            Zs[r1 * STZF + cl]     = tf32r(fmaxf(acc[mt][nt][2] + bx, 0.f));
            Zs[r1 * STZF + cl + 1] = tf32r(fmaxf(acc[mt][nt][3] + by, 0.f));
        }
    }
    __syncthreads();

    // phase2: h0 = z @ W2 + b2   (each warp: 16 rows x 32 cols)
    float acc2[4][4];
#pragma unroll
    for (int a = 0; a < 4; a++)
#pragma unroll
        for (int c = 0; c < 4; c++) acc2[a][c] = 0.f;

    const int rl0 = wid * 16 + gq;
#pragma unroll
    for (int ks = 0; ks < 32; ks++) {
        const int ko = ks * 8;
        uint32_t a[4];
        a[0] = Zs[rl0 * STZF + ko + tg];
        a[1] = Zs[(rl0 + 8) * STZF + ko + tg];
        a[2] = Zs[rl0 * STZF + ko + 4 + tg];
        a[3] = Zs[(rl0 + 8) * STZF + ko + 4 + tg];
#pragma unroll
        for (int nt = 0; nt < 4; nt++) {
            int n0 = nt * 8 + gq;
            uint32_t b[2];
            b[0] = W2s[n0 * STWF + ko + tg];
            b[1] = W2s[n0 * STWF + ko + 4 + tg];
            MMATF32(acc2[nt], a, b);
        }
    }

    int row0 = rowBase + rl0, row1 = row0 + 8;
#pragma unroll
    for (int nt = 0; nt < 4; nt++) {
        int cl = nt * 8 + 2 * tg;
        float bx = b2s[cl], by = b2s[cl + 1];
        if (row0 < N_NODES)
            *(float2*)(g_h0 + (size_t)row0 * N_CLS + cl) =
                make_float2(acc2[nt][0] + bx, acc2[nt][1] + by);
        if (row1 < N_NODES)
            *(float2*)(g_h0 + (size_t)row1 * N_CLS + cl) =
                make_float2(acc2[nt][2] + bx, acc2[nt][3] + by);
    }
}

// ---------------- scale: p_0 = fp16(dinv * h0) ----------------
__global__ void k_scale() {
    int i = blockIdx.x * blockDim.x + threadIdx.x;   // one half2 (2 classes)
    if (i >= N_NODES * 16) return;
    int n = i >> 4;
    float di = rsqrtf(1.0f + (float)g_deg[n]);
    float2 v = *(float2*)(g_h0 + (size_t)i * 2);
    g_ps[0][i] = __floats2half2_rn(v.x * di, v.y * di);
}

// ---------------- SpMV step: p_k = A_norm * p_{k-1} (2 nodes per warp) ----------------
__global__ __launch_bounds__(256) void k_spmv(int kidx) {
    const __half2* __restrict__ pc = g_ps[kidx - 1];
    __half2* __restrict__ pn = g_ps[kidx];

    const int NW = SPMV_BLOCKS * 8;   // total warps = 50000
    const int gw = blockIdx.x * 8 + (threadIdx.x >> 5);
    const int lane = threadIdx.x & 31;
    const int q = lane & 3;
    const int gslot = lane >> 2;

    for (int n = gw; n < N_NODES; n += NW) {
        int beg = g_rowptr[n], end = g_rowptr[n + 1];

        float acc[8];
#pragma unroll
        for (int j = 0; j < 8; j++) acc[j] = 0.f;

        int e = beg;
        for (; e + 16 <= end; e += 16) {
            int s0 = g_csr_idx[e + gslot];
            int s1 = g_csr_idx[e + 8 + gslot];
            uint4 r0 = *(const uint4*)(pc + (size_t)s0 * 16 + q * 4);
            uint4 r1 = *(const uint4*)(pc + (size_t)s1 * 16 + q * 4);
            float2 f;
            f = __half22float2(*(__half2*)&r0.x); acc[0] += f.x; acc[1] += f.y;
            f = __half22float2(*(__half2*)&r0.y); acc[2] += f.x; acc[3] += f.y;
            f = __half22float2(*(__half2*)&r0.z); acc[4] += f.x; acc[5] += f.y;
            f = __half22float2(*(__half2*)&r0.w); acc[6] += f.x; acc[7] += f.y;
            f = __half22float2(*(__half2*)&r1.x); acc[0] += f.x; acc[1] += f.y;
            f = __half22float2(*(__half2*)&r1.y); acc[2] += f.x; acc[3] += f.y;
            f = __half22float2(*(__half2*)&r1.z); acc[4] += f.x; acc[5] += f.y;
            f = __half22float2(*(__half2*)&r1.w); acc[6] += f.x; acc[7] += f.y;
        }
        for (; e < end; e += 8) {
            int ee = e + gslot;
            if (ee < end) {
                int s = g_csr_idx[ee];
                uint4 r0 = *(const uint4*)(pc + (size_t)s * 16 + q * 4);
                float2 f;
                f = __half22float2(*(__half2*)&r0.x); acc[0] += f.x; acc[1] += f.y;
                f = __half22float2(*(__half2*)&r0.y); acc[2] += f.x; acc[3] += f.y;
                f = __half22float2(*(__half2*)&r0.z); acc[4] += f.x; acc[5] += f.y;
                f = __half22float2(*(__half2*)&r0.w); acc[6] += f.x; acc[7] += f.y;
            }
        }

#pragma unroll
        for (int off = 4; off <= 16; off <<= 1) {
#pragma unroll
            for (int j = 0; j < 8; j++)
                acc[j] += __shfl_xor_sync(0xffffffffu, acc[j], off);
        }

        // self loop
        {
            uint4 r0 = *(const uint4*)(pc + (size_t)n * 16 + q * 4);
            float2 f;
            f = __half22float2(*(__half2*)&r0.x); acc[0] += f.x; acc[1] += f.y;
            f = __half22float2(*(__half2*)&r0.y); acc[2] += f.x; acc[3] += f.y;
            f = __half22float2(*(__half2*)&r0.z); acc[4] += f.x; acc[5] += f.y;
            f = __half22float2(*(__half2*)&r0.w); acc[6] += f.x; acc[7] += f.y;
        }

        if (gslot == 0) {
            float inv = 1.0f / (1.0f + (float)(end - beg));
            uint4 praw;
            __half2 t0 = __floats2half2_rn(acc[0] * inv, acc[1] * inv);
            __half2 t1 = __floats2half2_rn(acc[2] * inv, acc[3] * inv);
            __half2 t2 = __floats2half2_rn(acc[4] * inv, acc[5] * inv);
            __half2 t3 = __floats2half2_rn(acc[6] * inv, acc[7] * inv);
            praw.x = *(uint32_t*)&t0; praw.y = *(uint32_t*)&t1;
            praw.z = *(uint32_t*)&t2; praw.w = *(uint32_t*)&t3;
            *(uint4*)(pn + (size_t)n * 16 + q * 4) = praw;
        }
    }
}

// ---------------- final: out = log_softmax(gamma0*h0 + sum_k gamma_k*sqrt(deg1)*p_k) ----------------
__global__ void k_out(const float* __restrict__ gamma, float* __restrict__ out) {
    __shared__ float gs[KSTEPS + 1];
    int tid = threadIdx.x;
    if (tid <= KSTEPS) gs[tid] = gamma[tid];
    __syncthreads();

    int warp = tid >> 5, lane = tid & 31;
    int n = blockIdx.x * 8 + warp;
    if (n >= N_NODES) return;

    float sq = sqrtf(1.0f + (float)(g_rowptr[n + 1] - g_rowptr[n]));
    size_t o = (size_t)n * N_CLS + lane;
    float v = gs[0] * g_h0[o];
#pragma unroll
    for (int k = 1; k <= KSTEPS; k++)
        v += gs[k] * sq * __half2float(((const __half*)g_ps[k])[o]);

    float m = v;
#pragma unroll
    for (int off = 16; off; off >>= 1)
        m = fmaxf(m, __shfl_xor_sync(0xffffffffu, m, off));
    float e = expf(v - m);
    float sum = e;
#pragma unroll
    for (int off = 16; off; off >>= 1)
        sum += __shfl_xor_sync(0xffffffffu, sum, off);
    out[o] = v - m - logf(sum);
}

// ---------------- launch ----------------
extern "C" void kernel_launch(void* const* d_in, const int* in_sizes, int n_in,
                              void* d_out, int out_size) {
    const float* x     = (const float*)d_in[0];
    const void*  eiraw = d_in[1];
    const float* W1    = (const float*)d_in[2];
    const float* b1    = (const float*)d_in[3];
    const float* W2    = (const float*)d_in[4];
    const float* b2    = (const float*)d_in[5];
    const float* gamma = (const float*)d_in[6];
    float*       out   = (float*)d_out;

    // fork a side stream for the (independent) MLP chain
    cudaStream_t s2;
    cudaStreamCreateWithFlags(&s2, cudaStreamNonBlocking);
    cudaEvent_t eFork, eJoin;
    cudaEventCreateWithFlags(&eFork, cudaEventDisableTiming);
    cudaEventCreateWithFlags(&eJoin, cudaEventDisableTiming);

    cudaEventRecord(eFork, 0);
    cudaStreamWaitEvent(s2, eFork, 0);

    // side stream: weight conversion + MLP
    k_w1cvt<<<(F_IN * HID + 255) / 256, 256, 0, s2>>>(W1);
    k_w2cvt<<<(HID * N_CLS + 255) / 256, 256, 0, s2>>>(W2);
    cudaFuncSetAttribute(k_mlp, cudaFuncAttributeMaxDynamicSharedMemorySize, SMEM_T);
    k_mlp<<<(N_NODES + 127) / 128, 256, SMEM_T, s2>>>(x, b1, b2);
    cudaEventRecord(eJoin, s2);

    // main stream: edge preprocessing (raw edge list read directly)
    k_deg_zero<<<NBLK, 256>>>();
    k_sniff<<<1, 1>>>((const unsigned*)eiraw);
    k_degcnt<<<(N_EDGES + 255) / 256, 256>>>(eiraw);
    k_scan1<<<NBLK, 256>>>();
    k_scan2<<<1, 512>>>();
    k_scan3<<<NBLK, 256>>>();
    k_fill<<<(N_EDGES + 255) / 256, 256>>>(eiraw);

    // join: MLP results needed from here on
    cudaStreamWaitEvent(0, eJoin, 0);
    k_scale<<<(N_NODES * 16 + 255) / 256, 256>>>();

    for (int k = 1; k <= KSTEPS; k++)
        k_spmv<<<SPMV_BLOCKS, 256>>>(k);

    k_out<<<(N_NODES + 7) / 8, 256>>>(gamma, out);
}